// round 3
// baseline (speedup 1.0000x reference)
#include <cuda_runtime.h>
#include <cuda_bf16.h>
#include <cstdint>
#include <cstddef>

// ---------------- problem constants ----------------
#define HID   128
#define GSZ   512            // 4*H gate width
#define BATCH 1024
#define TLEN  512
#define DIN   12

#define K0    140            // D + H (layer 0 fused input+recurrent GEMV depth)
#define K1    256            // H + H (layer 1)
#define SR0   100            // weight rows resident in smem, layer 0
#define SR1   96             // weight rows resident in smem, layer 1
#define BT    8              // batch rows per block
#define NBLK  (BATCH / BT)   // 128 blocks

typedef unsigned long long ull;

// ---------------- device scratch (no-alloc rule: __device__ globals) ----------------
__device__ float g_W0T[K0 * GSZ];                  // [k][j] transposed weights, layer 0
__device__ float g_W1T[K1 * GSZ];                  // [k][j] transposed weights, layer 1
__device__ float g_bias0[GSZ];                     // b_ih0 + b_hh0
__device__ float g_bias1[GSZ];                     // b_ih1 + b_hh1
__device__ float g_h1[(size_t)TLEN * BATCH * HID]; // layer-0 hidden states (T,B,H)
__device__ float g_h2[BATCH * HID];                // layer-1 final hidden state

// ---------------- helpers ----------------
__device__ __forceinline__ ull dup2(float x) {
    ull d; asm("mov.b64 %0, {%1, %1};" : "=l"(d) : "f"(x)); return d;
}
__device__ __forceinline__ ull fma2(ull a, ull b, ull c) {
    ull d; asm("fma.rn.f32x2 %0, %1, %2, %3;" : "=l"(d) : "l"(a), "l"(b), "l"(c)); return d;
}
__device__ __forceinline__ float2 unp(ull v) {
    float2 r; asm("mov.b64 {%0, %1}, %2;" : "=f"(r.x), "=f"(r.y) : "l"(v)); return r;
}
__device__ __forceinline__ float sigm(float x) {
    return __fdividef(1.0f, 1.0f + __expf(-x));
}
__device__ __forceinline__ float tanh_f(float x) {
    return __fdividef(2.0f, 1.0f + __expf(-2.0f * x)) - 1.0f;
}

// ---------------- prep: transpose/concat weights + fold biases ----------------
__global__ void prep_kernel(const float* __restrict__ Wih0, const float* __restrict__ Whh0,
                            const float* __restrict__ bih0, const float* __restrict__ bhh0,
                            const float* __restrict__ Wih1, const float* __restrict__ Whh1,
                            const float* __restrict__ bih1, const float* __restrict__ bhh1) {
    int i = blockIdx.x * blockDim.x + threadIdx.x;
    if (i < K0 * GSZ) {
        int k = i / GSZ, j = i % GSZ;
        g_W0T[i] = (k < DIN) ? Wih0[j * DIN + k] : Whh0[j * HID + (k - DIN)];
    } else if (i < (K0 + K1) * GSZ) {
        int i2 = i - K0 * GSZ;
        int k = i2 / GSZ, j = i2 % GSZ;
        g_W1T[i2] = (k < HID) ? Wih1[j * HID + k] : Whh1[j * HID + (k - HID)];
    } else if (i < (K0 + K1) * GSZ + GSZ) {
        int j = i - (K0 + K1) * GSZ;
        g_bias0[j] = bih0[j] + bhh0[j];
    } else if (i < (K0 + K1) * GSZ + 2 * GSZ) {
        int j = i - (K0 + K1) * GSZ - GSZ;
        g_bias1[j] = bih1[j] + bhh1[j];
    }
}

// ---------------- fused LSTM layer ----------------
// One block = 8 batch rows, persistent over all T steps.
// Gate thread t owns columns j0=2t, j0+1; accumulators are f32x2 packed over
// batch-row pairs. Gate order (PyTorch): cols [0,128)=i [128,256)=f [256,384)=g [384,512)=o.
// Update thread t owns (b = t>>5, m = (t&31)+32q, q=0..3); c lives in its registers.
template <int LAYER>
__global__ void __launch_bounds__(256, 1)
lstm_kernel(const float* __restrict__ x) {
    constexpr int K    = (LAYER == 0) ? K0 : K1;
    constexpr int SR   = (LAYER == 0) ? SR0 : SR1;
    constexpr int KOFF = (LAYER == 0) ? DIN : HID;
    const float* __restrict__ WT   = (LAYER == 0) ? g_W0T : g_W1T;
    const float* __restrict__ bias = (LAYER == 0) ? g_bias0 : g_bias1;

    extern __shared__ float smem[];
    float* w_s = smem;                 // SR * 512
    float* v_s = smem + SR * GSZ;      // K * 12  (cols 0..7 used, pad for banks/align)
    float* g_s = v_s + K * 12;         // 8 * 512 gates [b][j]

    const int tid = threadIdx.x;
    const int b0  = blockIdx.x * BT;
    const int j0  = 2 * tid;

    // Preload resident weight rows into smem (once; amortized over 512 steps)
    {
        const float2* wsrc = (const float2*)WT;
        float2*       wdst = (float2*)w_s;
        for (int i = tid; i < SR * GSZ / 2; i += 256) wdst[i] = wsrc[i];
    }
    for (int i = tid; i < K * 12; i += 256) v_s[i] = 0.0f;  // h0 = 0

    const float2 bj = *(const float2*)&bias[j0];
    const ull bxd = dup2(bj.x);
    const ull byd = dup2(bj.y);

    const int ub = tid >> 5;   // update: batch row
    const int um = tid & 31;   // update: base hidden index
    float c_r[4] = {0.f, 0.f, 0.f, 0.f};

    for (int t = 0; t < TLEN; t++) {
        // ---- stage this step's inputs into v_s[0..KOFF) ----
        if (LAYER == 0) {
            if (tid < 96) {
                int bl = tid / 12, d = tid % 12;
                v_s[d * 12 + bl] = x[(((size_t)(b0 + bl)) * TLEN + t) * DIN + d];
            }
        } else {
            int r  = tid >> 5;
            int c2 = (tid & 31) * 2;
            const float* hrow = &g_h1[(((size_t)t) * BATCH + b0 + r) * HID];
            float2 a  = *(const float2*)&hrow[c2];
            float2 b2 = *(const float2*)&hrow[c2 + 64];
            v_s[(c2 + 0)  * 12 + r] = a.x;
            v_s[(c2 + 1)  * 12 + r] = a.y;
            v_s[(c2 + 64) * 12 + r] = b2.x;
            v_s[(c2 + 65) * 12 + r] = b2.y;
        }

        // ---- apply previous step's gates: update (h, c) ----
        if (t > 0) {
#pragma unroll
            for (int q = 0; q < 4; q++) {
                int m = um + 32 * q;
                float iv = sigm(g_s[ub * GSZ + m]);
                float fv = sigm(g_s[ub * GSZ + 128 + m]);
                float gv = tanh_f(g_s[ub * GSZ + 256 + m]);
                float ov = sigm(g_s[ub * GSZ + 384 + m]);
                float c  = fv * c_r[q] + iv * gv;
                c_r[q]   = c;
                float h  = ov * tanh_f(c);
                v_s[(KOFF + m) * 12 + ub] = h;
                if (LAYER == 0)
                    g_h1[(((size_t)(t - 1)) * BATCH + b0 + ub) * HID + m] = h;
            }
        }
        __syncthreads();

        // ---- gate GEMV: acc[col][bpair] over k ----
        ull a0 = bxd, a1 = bxd, a2 = bxd, a3 = bxd;   // col j0, pairs 0..3
        ull a4 = byd, a5 = byd, a6 = byd, a7 = byd;   // col j0+1

        // smem-resident weight rows
#pragma unroll 4
        for (int k = 0; k < SR; k++) {
            float2 w = *(const float2*)&w_s[k * GSZ + j0];
            ull w0 = dup2(w.x), w1 = dup2(w.y);
            ulonglong2 vA = *(const ulonglong2*)&v_s[k * 12];
            ulonglong2 vB = *(const ulonglong2*)&v_s[k * 12 + 4];
            a0 = fma2(w0, vA.x, a0); a1 = fma2(w0, vA.y, a1);
            a2 = fma2(w0, vB.x, a2); a3 = fma2(w0, vB.y, a3);
            a4 = fma2(w1, vA.x, a4); a5 = fma2(w1, vA.y, a5);
            a6 = fma2(w1, vB.x, a6); a7 = fma2(w1, vB.y, a7);
        }

        // remaining rows from L2, 8-deep register prefetch pipeline
        {
            float2 pf[8];
#pragma unroll
            for (int i = 0; i < 8; i++) pf[i] = *(const float2*)&WT[(SR + i) * GSZ + j0];
            for (int kc = SR; kc < K; kc += 8) {
                float2 cur[8];
#pragma unroll
                for (int i = 0; i < 8; i++) cur[i] = pf[i];
                if (kc + 8 < K) {
#pragma unroll
                    for (int i = 0; i < 8; i++)
                        pf[i] = *(const float2*)&WT[(kc + 8 + i) * GSZ + j0];
                }
#pragma unroll
                for (int i = 0; i < 8; i++) {
                    int k = kc + i;
                    ull w0 = dup2(cur[i].x), w1 = dup2(cur[i].y);
                    ulonglong2 vA = *(const ulonglong2*)&v_s[k * 12];
                    ulonglong2 vB = *(const ulonglong2*)&v_s[k * 12 + 4];
                    a0 = fma2(w0, vA.x, a0); a1 = fma2(w0, vA.y, a1);
                    a2 = fma2(w0, vB.x, a2); a3 = fma2(w0, vB.y, a3);
                    a4 = fma2(w1, vA.x, a4); a5 = fma2(w1, vA.y, a5);
                    a6 = fma2(w1, vB.x, a6); a7 = fma2(w1, vB.y, a7);
                }
            }
        }

        // ---- write gates to g_s[b][j] (conflict-free float2 stores) ----
        {
            ull ac0[4] = {a0, a1, a2, a3};
            ull ac1[4] = {a4, a5, a6, a7};
#pragma unroll
            for (int p = 0; p < 4; p++) {
                float2 u0 = unp(ac0[p]);
                float2 u1 = unp(ac1[p]);
                *(float2*)&g_s[(2 * p) * GSZ + j0]     = make_float2(u0.x, u1.x);
                *(float2*)&g_s[(2 * p + 1) * GSZ + j0] = make_float2(u0.y, u1.y);
            }
        }
        __syncthreads();
    }

    // ---- final update for t = T-1 ----
#pragma unroll
    for (int q = 0; q < 4; q++) {
        int m = um + 32 * q;
        float iv = sigm(g_s[ub * GSZ + m]);
        float fv = sigm(g_s[ub * GSZ + 128 + m]);
        float gv = tanh_f(g_s[ub * GSZ + 256 + m]);
        float ov = sigm(g_s[ub * GSZ + 384 + m]);
        float c  = fv * c_r[q] + iv * gv;
        float h  = ov * tanh_f(c);
        if (LAYER == 0)
            g_h1[(((size_t)(TLEN - 1)) * BATCH + b0 + ub) * HID + m] = h;
        else
            g_h2[(b0 + ub) * HID + m] = h;
    }
}

// ---------------- MLP head: relu(128->64) -> relu(64->32) -> 32->2 ----------------
__global__ void head_kernel(const float* __restrict__ W1, const float* __restrict__ b1,
                            const float* __restrict__ W2, const float* __restrict__ b2,
                            const float* __restrict__ W3, const float* __restrict__ b3,
                            float* __restrict__ out) {
    __shared__ float hrow[HID];
    __shared__ float z1[64];
    __shared__ float z2[32];
    int b   = blockIdx.x;
    int tid = threadIdx.x;  // 64 threads

    hrow[tid]      = g_h2[b * HID + tid];
    hrow[tid + 64] = g_h2[b * HID + tid + 64];
    __syncthreads();
    {
        float s = b1[tid];
        const float* w = &W1[tid * HID];
#pragma unroll 8
        for (int k = 0; k < HID; k++) s += w[k] * hrow[k];
        z1[tid] = fmaxf(s, 0.0f);
    }
    __syncthreads();
    if (tid < 32) {
        float s = b2[tid];
        const float* w = &W2[tid * 64];
#pragma unroll 8
        for (int k = 0; k < 64; k++) s += w[k] * z1[k];
        z2[tid] = fmaxf(s, 0.0f);
    }
    __syncthreads();
    if (tid < 2) {
        float s = b3[tid];
        const float* w = &W3[tid * 32];
#pragma unroll
        for (int k = 0; k < 32; k++) s += w[k] * z2[k];
        out[b * 2 + tid] = s;
    }
}

// ---------------- launch ----------------
extern "C" void kernel_launch(void* const* d_in, const int* in_sizes, int n_in,
                              void* d_out, int out_size) {
    const float* x    = (const float*)d_in[0];
    const float* Wih0 = (const float*)d_in[1];
    const float* Whh0 = (const float*)d_in[2];
    const float* bih0 = (const float*)d_in[3];
    const float* bhh0 = (const float*)d_in[4];
    const float* Wih1 = (const float*)d_in[5];
    const float* Whh1 = (const float*)d_in[6];
    const float* bih1 = (const float*)d_in[7];
    const float* bhh1 = (const float*)d_in[8];
    const float* W1   = (const float*)d_in[9];
    const float* b1   = (const float*)d_in[10];
    const float* W2   = (const float*)d_in[11];
    const float* b2   = (const float*)d_in[12];
    const float* W3   = (const float*)d_in[13];
    const float* b3   = (const float*)d_in[14];
    float* out = (float*)d_out;

    const int smem0 = (SR0 * GSZ + K0 * 12 + 8 * GSZ) * (int)sizeof(float);  // ~227.9 KB
    const int smem1 = (SR1 * GSZ + K1 * 12 + 8 * GSZ) * (int)sizeof(float);  // ~225.3 KB
    cudaFuncSetAttribute((const void*)lstm_kernel<0>,
                         cudaFuncAttributeMaxDynamicSharedMemorySize, smem0);
    cudaFuncSetAttribute((const void*)lstm_kernel<1>,
                         cudaFuncAttributeMaxDynamicSharedMemorySize, smem1);

    int tot = (K0 + K1) * GSZ + 2 * GSZ;
    prep_kernel<<<(tot + 255) / 256, 256>>>(Wih0, Whh0, bih0, bhh0,
                                            Wih1, Whh1, bih1, bhh1);
    lstm_kernel<0><<<NBLK, 256, smem0>>>(x);
    lstm_kernel<1><<<NBLK, 256, smem1>>>(nullptr);
    head_kernel<<<BATCH, 64>>>(W1, b1, W2, b2, W3, b3, out);
}

// round 4
// speedup vs baseline: 1.1204x; 1.1204x over previous
#include <cuda_runtime.h>
#include <cuda_bf16.h>
#include <cstdint>
#include <cstddef>

// ---------------- problem constants ----------------
#define HID   128
#define GSZ   512            // 4*H gate width
#define BATCH 1024
#define TLEN  512
#define DIN   12

#define KP0   144            // D + H padded to multiple of 8 (pad rows are zero)
#define KP1   256            // H + H (layer 1)
#define SRR   96             // weight rows resident in smem (both layers)
#define PRM   32             // weight rows resident in registers (both layers)
#define BT    8              // batch rows per block
#define NBLK  (BATCH / BT)   // 128 blocks

typedef unsigned long long ull;

// ---------------- device scratch (no-alloc rule: __device__ globals) ----------------
__device__ float g_W0T[KP0 * GSZ];                 // [k][j] transposed weights, layer 0
__device__ float g_W1T[KP1 * GSZ];                 // [k][j] transposed weights, layer 1
__device__ float g_bias0[GSZ];                     // b_ih0 + b_hh0
__device__ float g_bias1[GSZ];                     // b_ih1 + b_hh1
__device__ float g_h1[(size_t)TLEN * BATCH * HID]; // layer-0 hidden states (T,B,H)
__device__ float g_h2[BATCH * HID];                // layer-1 final hidden state

// ---------------- helpers ----------------
__device__ __forceinline__ ull dup2(float x) {
    ull d; asm("mov.b64 %0, {%1, %1};" : "=l"(d) : "f"(x)); return d;
}
__device__ __forceinline__ ull fma2(ull a, ull b, ull c) {
    ull d; asm("fma.rn.f32x2 %0, %1, %2, %3;" : "=l"(d) : "l"(a), "l"(b), "l"(c)); return d;
}
__device__ __forceinline__ float2 unp(ull v) {
    float2 r; asm("mov.b64 {%0, %1}, %2;" : "=f"(r.x), "=f"(r.y) : "l"(v)); return r;
}
__device__ __forceinline__ float sigm(float x) {
    return __fdividef(1.0f, 1.0f + __expf(-x));
}
__device__ __forceinline__ float tanh_f(float x) {
    return __fdividef(2.0f, 1.0f + __expf(-2.0f * x)) - 1.0f;
}

// one weight row's contribution to all 8 accumulators
#define FMA_ROW(W2V, KIDX)                                                    \
    do {                                                                      \
        ull w0 = dup2((W2V).x), w1 = dup2((W2V).y);                           \
        ulonglong2 vA = *(const ulonglong2*)&v_s[(KIDX) * 12];                \
        ulonglong2 vB = *(const ulonglong2*)&v_s[(KIDX) * 12 + 4];            \
        a0 = fma2(w0, vA.x, a0); a1 = fma2(w0, vA.y, a1);                     \
        a2 = fma2(w0, vB.x, a2); a3 = fma2(w0, vB.y, a3);                     \
        a4 = fma2(w1, vA.x, a4); a5 = fma2(w1, vA.y, a5);                     \
        a6 = fma2(w1, vB.x, a6); a7 = fma2(w1, vB.y, a7);                     \
    } while (0)

// ---------------- prep: transpose/concat weights + fold biases ----------------
__global__ void prep_kernel(const float* __restrict__ Wih0, const float* __restrict__ Whh0,
                            const float* __restrict__ bih0, const float* __restrict__ bhh0,
                            const float* __restrict__ Wih1, const float* __restrict__ Whh1,
                            const float* __restrict__ bih1, const float* __restrict__ bhh1) {
    int i = blockIdx.x * blockDim.x + threadIdx.x;
    if (i < KP0 * GSZ) {
        int k = i / GSZ, j = i % GSZ;
        float v = 0.0f;
        if (k < DIN)            v = Wih0[j * DIN + k];
        else if (k < DIN + HID) v = Whh0[j * HID + (k - DIN)];
        g_W0T[i] = v;                          // rows 140..143 stay zero (pad)
    } else if (i < (KP0 + KP1) * GSZ) {
        int i2 = i - KP0 * GSZ;
        int k = i2 / GSZ, j = i2 % GSZ;
        g_W1T[i2] = (k < HID) ? Wih1[j * HID + k] : Whh1[j * HID + (k - HID)];
    } else if (i < (KP0 + KP1) * GSZ + GSZ) {
        int j = i - (KP0 + KP1) * GSZ;
        g_bias0[j] = bih0[j] + bhh0[j];
    } else if (i < (KP0 + KP1) * GSZ + 2 * GSZ) {
        int j = i - (KP0 + KP1) * GSZ - GSZ;
        g_bias1[j] = bih1[j] + bhh1[j];
    }
}

// ---------------- fused LSTM layer ----------------
// One block = 8 batch rows, persistent over all T steps.
// Weight rows: [0,SRR) smem-resident, [SRR,SRR+PRM) register-resident,
// [SRR+PRM,KP) streamed from L2 with a rolling depth-3 register prefetch.
// Gate thread t owns columns j0=2t, j0+1; accumulators are f32x2 packed over
// batch-row pairs. Gate order (PyTorch): [0,128)=i [128,256)=f [256,384)=g [384,512)=o.
template <int LAYER>
__global__ void __launch_bounds__(256, 1)
lstm_kernel(const float* __restrict__ x) {
    constexpr int KP   = (LAYER == 0) ? KP0 : KP1;
    constexpr int KOFF = (LAYER == 0) ? DIN : HID;
    constexpr int SB   = SRR + PRM;            // stream base row
    constexpr int NG   = (KP - SB) / 8;        // stream groups (L0: 2, L1: 16)
    const float* __restrict__ WT   = (LAYER == 0) ? g_W0T : g_W1T;
    const float* __restrict__ bias = (LAYER == 0) ? g_bias0 : g_bias1;

    extern __shared__ float smem[];
    float* w_s = smem;                  // SRR * 512
    float* v_s = smem + SRR * GSZ;      // KP * 12 (cols 0..7 used; 12-stride for banks)
    float* g_s = v_s + KP * 12;         // 8 * 512 gates [b][j]

    const int tid = threadIdx.x;
    const int b0  = blockIdx.x * BT;
    const int j0  = 2 * tid;

    // smem-resident weight rows (loaded once, amortized over 512 steps)
    {
        const float2* wsrc = (const float2*)WT;
        float2*       wdst = (float2*)w_s;
        for (int i = tid; i < SRR * GSZ / 2; i += 256) wdst[i] = wsrc[i];
    }
    for (int i = tid; i < KP * 12; i += 256) v_s[i] = 0.0f;  // h0 = 0, pad rows = 0

    // register-resident weight rows (step-invariant)
    float2 pbuf[PRM];
#pragma unroll
    for (int i = 0; i < PRM; i++)
        pbuf[i] = *(const float2*)&WT[(SRR + i) * GSZ + j0];

    const float2 bj = *(const float2*)&bias[j0];
    const ull bxd = dup2(bj.x);
    const ull byd = dup2(bj.y);

    const int ub = tid >> 5;   // update phase: batch row
    const int um = tid & 31;   // update phase: base hidden index
    float c_r[4] = {0.f, 0.f, 0.f, 0.f};

    float2 rbuf[4][8];         // rolling stream buffers

    for (int t = 0; t < TLEN; t++) {
        // ---- issue stream prefetch for first groups (covered by update phase + smem loop) ----
        constexpr int PREG = (NG < 3) ? NG : 3;
#pragma unroll
        for (int gp = 0; gp < PREG; gp++)
#pragma unroll
            for (int i = 0; i < 8; i++)
                rbuf[gp][i] = *(const float2*)&WT[(SB + gp * 8 + i) * GSZ + j0];

        // ---- issue staging loads (x or h1) into registers ----
        float xstage = 0.0f;
        float2 hstA, hstB;
        int st_r = 0, st_c2 = 0;
        if (LAYER == 0) {
            if (tid < 96) {
                int bl = tid / 12, d = tid % 12;
                st_r = bl; st_c2 = d;
                xstage = x[(((size_t)(b0 + bl)) * TLEN + t) * DIN + d];
            }
        } else {
            st_r  = tid >> 5;
            st_c2 = (tid & 31) * 2;
            const float* hrow = &g_h1[(((size_t)t) * BATCH + b0 + st_r) * HID];
            hstA = *(const float2*)&hrow[st_c2];
            hstB = *(const float2*)&hrow[st_c2 + 64];
        }

        // ---- apply previous step's gates: update (h, c) ----
        if (t > 0) {
#pragma unroll
            for (int q = 0; q < 4; q++) {
                int m = um + 32 * q;
                float iv = sigm(g_s[ub * GSZ + m]);
                float fv = sigm(g_s[ub * GSZ + 128 + m]);
                float gv = tanh_f(g_s[ub * GSZ + 256 + m]);
                float ov = sigm(g_s[ub * GSZ + 384 + m]);
                float c  = fv * c_r[q] + iv * gv;
                c_r[q]   = c;
                float h  = ov * tanh_f(c);
                v_s[(KOFF + m) * 12 + ub] = h;
                if (LAYER == 0)
                    g_h1[(((size_t)(t - 1)) * BATCH + b0 + ub) * HID + m] = h;
            }
        }

        // ---- commit staged inputs to v_s ----
        if (LAYER == 0) {
            if (tid < 96) v_s[st_c2 * 12 + st_r] = xstage;
        } else {
            v_s[(st_c2 + 0)  * 12 + st_r] = hstA.x;
            v_s[(st_c2 + 1)  * 12 + st_r] = hstA.y;
            v_s[(st_c2 + 64) * 12 + st_r] = hstB.x;
            v_s[(st_c2 + 65) * 12 + st_r] = hstB.y;
        }
        __syncthreads();

        // ---- gate GEMV ----
        ull a0 = bxd, a1 = bxd, a2 = bxd, a3 = bxd;   // col j0
        ull a4 = byd, a5 = byd, a6 = byd, a7 = byd;   // col j0+1

        // 1) smem-resident rows
#pragma unroll 4
        for (int k = 0; k < SRR; k++) {
            float2 w = *(const float2*)&w_s[k * GSZ + j0];
            FMA_ROW(w, k);
        }

        // 2) register-resident rows
#pragma unroll
        for (int i = 0; i < PRM; i++)
            FMA_ROW(pbuf[i], SRR + i);

        // 3) streamed rows, rolling depth-3 prefetch (groups of 8)
        if constexpr (NG >= 4) {
#pragma unroll 1
            for (int g4 = 0; g4 < NG; g4 += 4) {
#pragma unroll
                for (int j = 0; j < 4; j++) {
                    int gp = g4 + j + 3;
                    if (gp < NG) {
#pragma unroll
                        for (int i = 0; i < 8; i++)
                            rbuf[(j + 3) & 3][i] =
                                *(const float2*)&WT[(SB + gp * 8 + i) * GSZ + j0];
                    }
                    int kb = SB + (g4 + j) * 8;
#pragma unroll
                    for (int i = 0; i < 8; i++)
                        FMA_ROW(rbuf[j][i], kb + i);
                }
            }
        } else {
#pragma unroll
            for (int g = 0; g < NG; g++) {
                int kb = SB + g * 8;
#pragma unroll
                for (int i = 0; i < 8; i++)
                    FMA_ROW(rbuf[g][i], kb + i);
            }
        }

        // ---- write gates to g_s[b][j] (conflict-free float2 stores) ----
        {
            ull ac0[4] = {a0, a1, a2, a3};
            ull ac1[4] = {a4, a5, a6, a7};
#pragma unroll
            for (int p = 0; p < 4; p++) {
                float2 u0 = unp(ac0[p]);
                float2 u1 = unp(ac1[p]);
                *(float2*)&g_s[(2 * p) * GSZ + j0]     = make_float2(u0.x, u1.x);
                *(float2*)&g_s[(2 * p + 1) * GSZ + j0] = make_float2(u0.y, u1.y);
            }
        }
        __syncthreads();
    }

    // ---- final update for t = T-1 ----
#pragma unroll
    for (int q = 0; q < 4; q++) {
        int m = um + 32 * q;
        float iv = sigm(g_s[ub * GSZ + m]);
        float fv = sigm(g_s[ub * GSZ + 128 + m]);
        float gv = tanh_f(g_s[ub * GSZ + 256 + m]);
        float ov = sigm(g_s[ub * GSZ + 384 + m]);
        float c  = fv * c_r[q] + iv * gv;
        float h  = ov * tanh_f(c);
        if (LAYER == 0)
            g_h1[(((size_t)(TLEN - 1)) * BATCH + b0 + ub) * HID + m] = h;
        else
            g_h2[(b0 + ub) * HID + m] = h;
    }
}

// ---------------- MLP head: relu(128->64) -> relu(64->32) -> 32->2 ----------------
__global__ void head_kernel(const float* __restrict__ W1, const float* __restrict__ b1,
                            const float* __restrict__ W2, const float* __restrict__ b2,
                            const float* __restrict__ W3, const float* __restrict__ b3,
                            float* __restrict__ out) {
    __shared__ float hrow[HID];
    __shared__ float z1[64];
    __shared__ float z2[32];
    int b   = blockIdx.x;
    int tid = threadIdx.x;  // 64 threads

    hrow[tid]      = g_h2[b * HID + tid];
    hrow[tid + 64] = g_h2[b * HID + tid + 64];
    __syncthreads();
    {
        float s = b1[tid];
        const float* w = &W1[tid * HID];
#pragma unroll 8
        for (int k = 0; k < HID; k++) s += w[k] * hrow[k];
        z1[tid] = fmaxf(s, 0.0f);
    }
    __syncthreads();
    if (tid < 32) {
        float s = b2[tid];
        const float* w = &W2[tid * 64];
#pragma unroll 8
        for (int k = 0; k < 64; k++) s += w[k] * z1[k];
        z2[tid] = fmaxf(s, 0.0f);
    }
    __syncthreads();
    if (tid < 2) {
        float s = b3[tid];
        const float* w = &W3[tid * 32];
#pragma unroll
        for (int k = 0; k < 32; k++) s += w[k] * z2[k];
        out[b * 2 + tid] = s;
    }
}

// ---------------- launch ----------------
extern "C" void kernel_launch(void* const* d_in, const int* in_sizes, int n_in,
                              void* d_out, int out_size) {
    const float* x    = (const float*)d_in[0];
    const float* Wih0 = (const float*)d_in[1];
    const float* Whh0 = (const float*)d_in[2];
    const float* bih0 = (const float*)d_in[3];
    const float* bhh0 = (const float*)d_in[4];
    const float* Wih1 = (const float*)d_in[5];
    const float* Whh1 = (const float*)d_in[6];
    const float* bih1 = (const float*)d_in[7];
    const float* bhh1 = (const float*)d_in[8];
    const float* W1   = (const float*)d_in[9];
    const float* b1   = (const float*)d_in[10];
    const float* W2   = (const float*)d_in[11];
    const float* b2   = (const float*)d_in[12];
    const float* W3   = (const float*)d_in[13];
    const float* b3   = (const float*)d_in[14];
    float* out = (float*)d_out;

    const int smem0 = (SRR * GSZ + KP0 * 12 + 8 * GSZ) * (int)sizeof(float);  // 219,904 B
    const int smem1 = (SRR * GSZ + KP1 * 12 + 8 * GSZ) * (int)sizeof(float);  // 225,280 B
    cudaFuncSetAttribute((const void*)lstm_kernel<0>,
                         cudaFuncAttributeMaxDynamicSharedMemorySize, smem0);
    cudaFuncSetAttribute((const void*)lstm_kernel<1>,
                         cudaFuncAttributeMaxDynamicSharedMemorySize, smem1);

    int tot = (KP0 + KP1) * GSZ + 2 * GSZ;
    prep_kernel<<<(tot + 255) / 256, 256>>>(Wih0, Whh0, bih0, bhh0,
                                            Wih1, Whh1, bih1, bhh1);
    lstm_kernel<0><<<NBLK, 256, smem0>>>(x);
    lstm_kernel<1><<<NBLK, 256, smem1>>>(nullptr);
    head_kernel<<<BATCH, 64>>>(W1, b1, W2, b2, W3, b3, out);
}